// round 17
// baseline (speedup 1.0000x reference)
#include <cuda_runtime.h>
#include <math.h>

// ---------------------------------------------------------------------------
// 3-layer LSTM (H=51) + linear(2) head, B=1024, T=2048, persistent kernel.
// FLAG-SYNCED PIPELINE, SPLIT INTO 2 INDEPENDENT BATCH-HALF CHAINS:
//   warps 0-3  : layer-1 (halves: w0-1 / w2-3), 51 thr/half, 4 batches/thr
//   warps 4-7  : layer-2 (same split)
//   warps 8-11 : layer-0
//   warp  12   : head (both halves) + XS staging; warp 13 exits
// h0/h1 triple-buffered (slack 2), h2 double. Per-(layer,half) counters +
// 64-thread named barriers. Matrices trimmed to 204 rows (no padded unit).
// fma.rn.f32x2 k-pairs, full K per thread, 16 u64 accumulators.
// ---------------------------------------------------------------------------

#define Hn    51
#define Tn    2048
#define NBb   8
#define NCTA  128
#define NT    448
#define ABST  52                 // act batch-row stride
#define HB    416                // floats per h buffer (8*52)
#define MROW  52
#define MSZ   (204 * MROW)       // 10608
#define GST   (Hn * MROW)        // 2652: gate-block stride

// SMEM float offsets
#define O_WHH0 0
#define O_WIH1 10608
#define O_WHH1 21216
#define O_WIH2 31824
#define O_WHH2 42432
#define O_BIAS 53040             // [3][204]
#define O_WLIN 53652             // [2][52]
#define O_BLIN 53756             // 2 (+2 pad)
#define O_H0   53760             // 3 bufs * 416
#define O_H1   (O_H0 + 3*HB)     // 55008
#define O_H2   (O_H1 + 3*HB)     // 56256, 2 bufs
#define O_XS   (O_H2 + 2*HB)     // 57088: [2][256]
#define O_CNT  (O_XS + 512)      // 57600: ints c0[2],c1[2],c2[2],ch[2],cw
#define SM_FLOATS (O_CNT + 16)   // 57616
#define SM_BYTES  (SM_FLOATS * 4)   // 230464 <= 232448

typedef unsigned long long ull;

__device__ __forceinline__ void f2(ull& a, ull w, ull v) {
    asm("fma.rn.f32x2 %0, %1, %2, %0;" : "+l"(a) : "l"(w), "l"(v));
}
__device__ __forceinline__ float hadd(ull v) {
    unsigned lo, hi;
    asm("mov.b64 {%0,%1}, %2;" : "=r"(lo), "=r"(hi) : "l"(v));
    return __uint_as_float(lo) + __uint_as_float(hi);
}
__device__ __forceinline__ float fsig(float x) {
    return __fdividef(1.0f, 1.0f + __expf(-x));
}
__device__ __forceinline__ float ftanh(float x) {
    return __fdividef(2.0f, 1.0f + __expf(-2.0f * x)) - 1.0f;
}
__device__ __forceinline__ void waitge(volatile int* c, int v) {
    if (v > 0) { while (*c < v) __nanosleep(20); }
    asm volatile("" ::: "memory");
}
#define NBAR64(id) asm volatile("bar.sync %0, 64;" :: "r"(id) : "memory")

__global__ void __launch_bounds__(NT, 1) lstm_pers(
    const float* __restrict__ xin,  const float* __restrict__ tin,
    const float* __restrict__ Wih0, const float* __restrict__ Whh0,
    const float* __restrict__ bih0, const float* __restrict__ bhh0,
    const float* __restrict__ Wih1, const float* __restrict__ Whh1,
    const float* __restrict__ bih1, const float* __restrict__ bhh1,
    const float* __restrict__ Wih2, const float* __restrict__ Whh2,
    const float* __restrict__ bih2, const float* __restrict__ bhh2,
    const float* __restrict__ Wlin, const float* __restrict__ blin,
    float* __restrict__ out)
{
    extern __shared__ float sm[];
    const int tid   = threadIdx.x;
    const int bbase = blockIdx.x * NBb;
    volatile int* cnt = (volatile int*)(sm + O_CNT);

    // ---- one-time staging (204-row matrices, col 51 = 0) ----
    {
        const float* srcs[5] = {Whh0, Wih1, Whh1, Wih2, Whh2};
        const int    dsts[5] = {O_WHH0, O_WIH1, O_WHH1, O_WIH2, O_WHH2};
        for (int w = 0; w < 5; w++) {
            const float* s = srcs[w];
            float*       d = sm + dsts[w];
            for (int i = tid; i < MSZ; i += NT) {
                int r = i / MROW, k = i - r * MROW;
                d[i] = (k < Hn) ? s[r * Hn + k] : 0.0f;
            }
        }
    }
    {
        const float* bi[3] = {bih0, bih1, bih2};
        const float* bh[3] = {bhh0, bhh1, bhh2};
        for (int i = tid; i < 3 * 204; i += NT) {
            int lay = i / 204, r = i - lay * 204;
            sm[O_BIAS + i] = bi[lay][r] + bh[lay][r];
        }
    }
    for (int i = tid; i < 2 * MROW; i += NT) {
        int r = i / MROW, k = i - r * MROW;
        sm[O_WLIN + i] = (k < Hn) ? Wlin[r * Hn + k] : 0.0f;
    }
    if (tid < 2) sm[O_BLIN + tid] = blin[tid];
    for (int i = tid; i < 8 * HB; i += NT) sm[O_H0 + i] = 0.0f;
    if (tid < 256) {                       // window 0 into XS buf 0
        int tt = tid >> 4, col = tid & 15;
        float v;
        if (col < 8) v = xin[(size_t)(bbase + col) * Tn + tt];
        else         v = tin[(size_t)(bbase + col - 8) * Tn + tt];
        sm[O_XS + tid] = v;
    }
    if (tid < 16) ((int*)(sm + O_CNT))[tid] = (tid == 8) ? 1 : 0;  // cw=1
    __syncthreads();                       // the ONLY CTA-wide barrier

    const int wid = tid >> 5;
    int grp, lt;
    if (wid < 4)       { grp = 1; lt = tid; }
    else if (wid < 8)  { grp = 2; lt = tid - 128; }
    else if (wid < 12) { grp = 0; lt = tid - 256; }
    else if (wid == 12){ grp = 3; lt = tid - 384; }
    else               { return; }

    const int half = lt >> 6;              // 0 or 1
    const int u    = lt & 63;
    const bool on  = (grp != 3) && (u < Hn);
    const int j    = on ? u : 0;
    const int ob0  = half * 4;             // own 4 batches
    const int act0 = ob0 * ABST;

    const float* wmA;  const float* wmB;
    if (grp == 1)      { wmA = sm + O_WIH1 + j * MROW; wmB = sm + O_WHH1 + j * MROW; }
    else if (grp == 2) { wmA = sm + O_WIH2 + j * MROW; wmB = sm + O_WHH2 + j * MROW; }
    else               { wmA = sm + O_WHH0 + j * MROW; wmB = wmA; }

    float bsv[4];
    #pragma unroll
    for (int g = 0; g < 4; g++)
        bsv[g] = on ? sm[O_BIAS + grp * 204 + g * Hn + j] : 0.0f;

    float wx[8];
    #pragma unroll
    for (int i = 0; i < 8; i++) wx[i] = 0.0f;
    if (grp == 0 && on) {
        #pragma unroll
        for (int g = 0; g < 4; g++) {
            wx[g*2+0] = Wih0[(g*Hn + j)*2 + 0];
            wx[g*2+1] = Wih0[(g*Hn + j)*2 + 1];
        }
    }

    float cs[4];
    #pragma unroll
    for (int i = 0; i < 4; i++) cs[i] = 0.0f;

    // counters: c0=0+half, c1=2+half, c2=4+half, ch=6+half, cw=8
    if (grp == 1) {
        const int cIn = 0 + half, cDn = 4 + half, cMe = 2 + half;
        const int bid = 1 + half;
        int bc = 0, bp = 2;                       // s%3, (s-1)%3
        for (int s = 0; s < Tn; s++) {
            waitge(cnt + cIn, s + 1);             // h0(s) ready
            waitge(cnt + cDn, s - 2);             // h1 buf free (g2 done s-3)
            if (on) {
                const float* xa = sm + O_H0 + bc * HB + act0;
                const float* ha = sm + O_H1 + bp * HB + act0;
                float*       hd = sm + O_H1 + bc * HB;
                ull acc[16];
                #pragma unroll
                for (int ii = 0; ii < 16; ii++) acc[ii] = 0ull;
                #pragma unroll
                for (int c = 0; c < 13; c++) {
                    ulonglong2 x0 = *(const ulonglong2*)(xa + 0*ABST + c*4);
                    ulonglong2 x1 = *(const ulonglong2*)(xa + 1*ABST + c*4);
                    ulonglong2 x2 = *(const ulonglong2*)(xa + 2*ABST + c*4);
                    ulonglong2 x3 = *(const ulonglong2*)(xa + 3*ABST + c*4);
                    ulonglong2 h0 = *(const ulonglong2*)(ha + 0*ABST + c*4);
                    ulonglong2 h1 = *(const ulonglong2*)(ha + 1*ABST + c*4);
                    ulonglong2 h2 = *(const ulonglong2*)(ha + 2*ABST + c*4);
                    ulonglong2 h3 = *(const ulonglong2*)(ha + 3*ABST + c*4);
                    #pragma unroll
                    for (int g = 0; g < 4; g++) {
                        ulonglong2 wi = *(const ulonglong2*)(wmA + g*GST + c*4);
                        ulonglong2 wh = *(const ulonglong2*)(wmB + g*GST + c*4);
                        f2(acc[g*4+0], wi.x, x0.x); f2(acc[g*4+0], wi.y, x0.y);
                        f2(acc[g*4+1], wi.x, x1.x); f2(acc[g*4+1], wi.y, x1.y);
                        f2(acc[g*4+2], wi.x, x2.x); f2(acc[g*4+2], wi.y, x2.y);
                        f2(acc[g*4+3], wi.x, x3.x); f2(acc[g*4+3], wi.y, x3.y);
                        f2(acc[g*4+0], wh.x, h0.x); f2(acc[g*4+0], wh.y, h0.y);
                        f2(acc[g*4+1], wh.x, h1.x); f2(acc[g*4+1], wh.y, h1.y);
                        f2(acc[g*4+2], wh.x, h2.x); f2(acc[g*4+2], wh.y, h2.y);
                        f2(acc[g*4+3], wh.x, h3.x); f2(acc[g*4+3], wh.y, h3.y);
                    }
                }
                float p[16];
                #pragma unroll
                for (int ii = 0; ii < 16; ii++)
                    p[ii] = hadd(acc[ii]) + bsv[ii >> 2];
                #pragma unroll
                for (int i = 0; i < 4; i++) {
                    float cn = fsig(p[4+i]) * cs[i] + fsig(p[0+i]) * ftanh(p[8+i]);
                    cs[i] = cn;
                    hd[(ob0 + i) * ABST + j] = fsig(p[12+i]) * ftanh(cn);
                }
            }
            NBAR64(bid);
            if (u == 0) cnt[cMe] = s + 1;
            bp = bc; if (++bc == 3) bc = 0;
        }
    } else if (grp == 2) {
        const int cIn = 2 + half, cDn = 6 + half, cMe = 4 + half;
        const int bid = 3 + half;
        int bc = 0;                               // r%3 (x buffer)
        for (int r = 0; r < Tn; r++) {
            waitge(cnt + cIn, r + 1);             // h1(r) ready
            waitge(cnt + cDn, r - 1);             // h2 buf free (head done r-2)
            if (on) {
                const float* xa = sm + O_H1 + bc * HB + act0;
                const float* ha = sm + O_H2 + ((r & 1) ^ 1) * HB + act0;
                float*       hd = sm + O_H2 + (r & 1) * HB;
                ull acc[16];
                #pragma unroll
                for (int ii = 0; ii < 16; ii++) acc[ii] = 0ull;
                #pragma unroll
                for (int c = 0; c < 13; c++) {
                    ulonglong2 x0 = *(const ulonglong2*)(xa + 0*ABST + c*4);
                    ulonglong2 x1 = *(const ulonglong2*)(xa + 1*ABST + c*4);
                    ulonglong2 x2 = *(const ulonglong2*)(xa + 2*ABST + c*4);
                    ulonglong2 x3 = *(const ulonglong2*)(xa + 3*ABST + c*4);
                    ulonglong2 h0 = *(const ulonglong2*)(ha + 0*ABST + c*4);
                    ulonglong2 h1 = *(const ulonglong2*)(ha + 1*ABST + c*4);
                    ulonglong2 h2 = *(const ulonglong2*)(ha + 2*ABST + c*4);
                    ulonglong2 h3 = *(const ulonglong2*)(ha + 3*ABST + c*4);
                    #pragma unroll
                    for (int g = 0; g < 4; g++) {
                        ulonglong2 wi = *(const ulonglong2*)(wmA + g*GST + c*4);
                        ulonglong2 wh = *(const ulonglong2*)(wmB + g*GST + c*4);
                        f2(acc[g*4+0], wi.x, x0.x); f2(acc[g*4+0], wi.y, x0.y);
                        f2(acc[g*4+1], wi.x, x1.x); f2(acc[g*4+1], wi.y, x1.y);
                        f2(acc[g*4+2], wi.x, x2.x); f2(acc[g*4+2], wi.y, x2.y);
                        f2(acc[g*4+3], wi.x, x3.x); f2(acc[g*4+3], wi.y, x3.y);
                        f2(acc[g*4+0], wh.x, h0.x); f2(acc[g*4+0], wh.y, h0.y);
                        f2(acc[g*4+1], wh.x, h1.x); f2(acc[g*4+1], wh.y, h1.y);
                        f2(acc[g*4+2], wh.x, h2.x); f2(acc[g*4+2], wh.y, h2.y);
                        f2(acc[g*4+3], wh.x, h3.x); f2(acc[g*4+3], wh.y, h3.y);
                    }
                }
                float p[16];
                #pragma unroll
                for (int ii = 0; ii < 16; ii++)
                    p[ii] = hadd(acc[ii]) + bsv[ii >> 2];
                #pragma unroll
                for (int i = 0; i < 4; i++) {
                    float cn = fsig(p[4+i]) * cs[i] + fsig(p[0+i]) * ftanh(p[8+i]);
                    cs[i] = cn;
                    hd[(ob0 + i) * ABST + j] = fsig(p[12+i]) * ftanh(cn);
                }
            }
            NBAR64(bid);
            if (u == 0) cnt[cMe] = r + 1;
            if (++bc == 3) bc = 0;
        }
    } else if (grp == 0) {
        const int cMe = 0 + half;
        const int bid = 5 + half;
        int bc = 0, bp = 2;
        for (int t = 0; t < Tn; t++) {
            waitge(cnt + 8, (t >> 4) + 1);        // input window staged
            waitge(cnt + 2 + half, t - 2);        // h0 buf free (g1 done t-3)
            if (on) {
                const int tc = t & 15, xb = (t >> 4) & 1;
                const float* ha = sm + O_H0 + bp * HB + act0;
                float*       hd = sm + O_H0 + bc * HB;
                ull acc[16];
                #pragma unroll
                for (int ii = 0; ii < 16; ii++) acc[ii] = 0ull;
                #pragma unroll
                for (int c = 0; c < 13; c++) {
                    ulonglong2 a0 = *(const ulonglong2*)(ha + 0*ABST + c*4);
                    ulonglong2 a1 = *(const ulonglong2*)(ha + 1*ABST + c*4);
                    ulonglong2 a2 = *(const ulonglong2*)(ha + 2*ABST + c*4);
                    ulonglong2 a3 = *(const ulonglong2*)(ha + 3*ABST + c*4);
                    #pragma unroll
                    for (int g = 0; g < 4; g++) {
                        ulonglong2 w = *(const ulonglong2*)(wmA + g*GST + c*4);
                        f2(acc[g*4+0], w.x, a0.x); f2(acc[g*4+0], w.y, a0.y);
                        f2(acc[g*4+1], w.x, a1.x); f2(acc[g*4+1], w.y, a1.y);
                        f2(acc[g*4+2], w.x, a2.x); f2(acc[g*4+2], w.y, a2.y);
                        f2(acc[g*4+3], w.x, a3.x); f2(acc[g*4+3], w.y, a3.y);
                    }
                }
                float p[16];
                #pragma unroll
                for (int ii = 0; ii < 16; ii++)
                    p[ii] = hadd(acc[ii]) + bsv[ii >> 2];
                #pragma unroll
                for (int i = 0; i < 4; i++) {
                    float xv = sm[O_XS + xb*256 + tc*16 + ob0 + i];
                    float tv = sm[O_XS + xb*256 + tc*16 + 8 + ob0 + i];
                    float pi = p[0+i]  + wx[0]*xv + wx[1]*tv;
                    float pf = p[4+i]  + wx[2]*xv + wx[3]*tv;
                    float pg = p[8+i]  + wx[4]*xv + wx[5]*tv;
                    float pq = p[12+i] + wx[6]*xv + wx[7]*tv;
                    float cn = fsig(pf) * cs[i] + fsig(pi) * ftanh(pg);
                    cs[i] = cn;
                    hd[(ob0 + i) * ABST + j] = fsig(pq) * ftanh(cn);
                }
            }
            NBAR64(bid);
            if (u == 0) cnt[cMe] = t + 1;
            bp = bc; if (++bc == 3) bc = 0;
        }
    } else {
        // ---- head warp: outputs (both halves) + input staging ----
        const int lane = lt;
        for (int q = 0; q < Tn; q++) {
            waitge(cnt + 4, q + 1);               // h2(q) half 0
            waitge(cnt + 5, q + 1);               // h2(q) half 1
            if ((q & 15) == 8) {
                const int wn = (q >> 4) + 1;
                if (wn * 16 < Tn) {
                    const int dst = O_XS + (wn & 1) * 256;
                    #pragma unroll
                    for (int it = 0; it < 8; it++) {
                        int i = lane + it * 32;
                        int tt = i >> 4, col = i & 15;
                        float v;
                        if (col < 8) v = xin[(size_t)(bbase + col) * Tn + wn*16 + tt];
                        else         v = tin[(size_t)(bbase + col - 8) * Tn + wn*16 + tt];
                        sm[dst + i] = v;
                    }
                    __syncwarp();
                    asm volatile("membar.cta;" ::: "memory");
                    if (lane == 0) cnt[8] = wn + 1;
                }
            }
            if (lane < 16) {
                int bb = lane >> 1, o = lane & 1;
                const float* hh = sm + O_H2 + (q & 1) * HB + bb * ABST;
                const float* w  = sm + O_WLIN + o * MROW;
                float ssum = sm[O_BLIN + o];
                #pragma unroll
                for (int k = 0; k < Hn; k++) ssum += w[k] * hh[k];
                if (o) ssum = (ssum > 30.0f) ? ssum : log1pf(expf(ssum));
                out[(((size_t)(bbase + bb)) * Tn + (size_t)q) * 2 + o] = ssum;
            }
            __syncwarp();
            if (lane == 0) { cnt[6] = q + 1; cnt[7] = q + 1; }
        }
    }
}

extern "C" void kernel_launch(void* const* d_in, const int* in_sizes, int n_in,
                              void* d_out, int out_size)
{
    (void)in_sizes; (void)n_in; (void)out_size;
    cudaFuncSetAttribute(lstm_pers, cudaFuncAttributeMaxDynamicSharedMemorySize,
                         SM_BYTES);
    lstm_pers<<<NCTA, NT, SM_BYTES>>>(
        (const float*)d_in[0],  (const float*)d_in[1],
        (const float*)d_in[2],  (const float*)d_in[3],
        (const float*)d_in[4],  (const float*)d_in[5],
        (const float*)d_in[6],  (const float*)d_in[7],
        (const float*)d_in[8],  (const float*)d_in[9],
        (const float*)d_in[10], (const float*)d_in[11],
        (const float*)d_in[12], (const float*)d_in[13],
        (const float*)d_in[14], (const float*)d_in[15],
        (float*)d_out);
}